// round 9
// baseline (speedup 1.0000x reference)
#include <cuda_runtime.h>
#include <cuda_bf16.h>
#include <cstdint>

// Problem constants
#define BB 2
#define NN 65536
#define CC 256
#define HH 8
#define DD 64
#define SS 64
#define INNERD 512
#define NTOK (BB * NN)      // 131072
#define NCTA (NTOK / 128)   // 1024

// smem layout (bytes). Strides (words): A=264, slab=72, w/f=136 (all ==8 mod 32 -> conflict-free LDS.64)
#define AST 264
#define OFF_A   1024
#define A_BYTES (128 * AST * 4)          // 135168
#define OFF_L0  (OFF_A + A_BYTES)        // 136192
#define SLABB   18432                    // 64 rows * 72 words * 4
#define OFF_L1  (OFF_L0 + SLABB)
#define OFF_H0  (OFF_L1 + SLABB)
#define OFF_H1  (OFF_H0 + SLABB)
#define OFF_W   OFF_L0                   // w 64x136x4 = 34816 <= 36864
#define OFF_F   OFF_H0
#define SMEM_TOTAL (OFF_H1 + SLABB)      // 209920

// Device scratch
__device__ __align__(16) float g_Weff[HH][CC][SS];
__device__ __align__(16) float g_beff[HH][SS];
__device__ __align__(16) float g_acc[BB * HH * SS * DD];
__device__ __align__(16) float g_norm[BB * HH * SS];
__device__ __align__(16) float g_Btf[HH * 128 * CC];   // tf32-rounded, k-permuted B^T images

// ---------------- helpers ----------------
__device__ __forceinline__ uint32_t cvt_tf32(float v) {
    uint32_t r;
    asm("cvt.rna.tf32.f32 %0, %1;" : "=r"(r) : "f"(v));
    return r;
}
__device__ __forceinline__ void mma_tf32(float* c, const uint32_t* a,
                                         uint32_t b0, uint32_t b1) {
    asm volatile(
        "mma.sync.aligned.m16n8k8.row.col.f32.tf32.tf32.f32 "
        "{%0,%1,%2,%3}, {%4,%5,%6,%7}, {%8,%9}, {%0,%1,%2,%3};"
        : "+f"(c[0]), "+f"(c[1]), "+f"(c[2]), "+f"(c[3])
        : "r"(a[0]), "r"(a[1]), "r"(a[2]), "r"(a[3]), "r"(b0), "r"(b1));
}
__device__ __forceinline__ uint32_t smem_u32(const void* p) {
    uint32_t a;
    asm("{ .reg .u64 t; cvta.to.shared.u64 t, %1; cvt.u32.u64 %0, t; }" : "=r"(a) : "l"(p));
    return a;
}
#define CP_ASYNC16(dst, src) \
    asm volatile("cp.async.cg.shared.global [%0], [%1], 16;" :: "r"(dst), "l"(src))
#define CP_COMMIT()  asm volatile("cp.async.commit_group;" ::: "memory")
#define CP_WAIT1()   asm volatile("cp.async.wait_group 1;" ::: "memory")
#define CP_WAIT0()   asm volatile("cp.async.wait_group 0;" ::: "memory")
#define HALF_BAR(id) asm volatile("bar.sync %0, 128;" :: "r"(id) : "memory")

// ---------------------------------------------------------------- zero
__global__ void zero_kernel() {
    int i = blockIdx.x * blockDim.x + threadIdx.x;
    if (i < BB * HH * SS * DD) g_acc[i] = 0.0f;
    if (i < BB * HH * SS)      g_norm[i] = 0.0f;
}

// ------------------------------------------------- precompute Weff/beff
__global__ void precompute_kernel(const float* __restrict__ Wx,
                                  const float* __restrict__ bx,
                                  const float* __restrict__ Wslice,
                                  const float* __restrict__ bslice) {
    int m = blockIdx.x;
    int s = threadIdx.x;
    if (m < HH * CC) {
        int h = m / CC, k = m % CC;
        float a = 0.0f;
#pragma unroll 16
        for (int d = 0; d < DD; d++)
            a += Wx[(size_t)k * INNERD + h * DD + d] * Wslice[d * SS + s];
        g_Weff[h][k][s] = a;
    } else {
        for (int h = 0; h < HH; h++) {
            float a = bslice[s];
            for (int d = 0; d < DD; d++)
                a += bx[h * DD + d] * Wslice[d * SS + s];
            g_beff[h][s] = a;
        }
    }
}

// ---- B^T images [h][n(64 s | 64 d)][K perm-within-8], tf32-rounded
__global__ void build_bt(const float* __restrict__ Wfx) {
    int h = blockIdx.x;
    for (int i = threadIdx.x; i < 128 * 256; i += 256) {
        int n = i >> 8, K = i & 255;
        float v = (n < 64) ? g_Weff[h][K][n]
                           : Wfx[(size_t)K * INNERD + h * DD + (n - 64)];
        int pos = (K & ~7) + ((K & 3) << 1) + ((K >> 2) & 1);
        g_Btf[(size_t)(h * 128 + n) * 256 + pos] = __uint_as_float(cvt_tf32(v));
    }
}

// ---------------------------------------------------------------- main
extern __shared__ unsigned char smem[];

__global__ __launch_bounds__(256, 1) void fused_main(
    const float* __restrict__ x,
    const float* __restrict__ bfx,
    const float* __restrict__ temperature)
{
    const uint32_t smb = smem_u32(smem);
    const int ct   = blockIdx.x;
    const int t    = threadIdx.x;
    const int wp   = t >> 5;
    const int lane = t & 31;
    const int g    = lane >> 2;
    const int q    = lane & 3;
    const int half = wp >> 2;         // 0: s-half (n 0..63), 1: d-half
    const int wml  = wp & 3;          // m-group (32 tok)
    const int t128 = t & 127;
    const int tok0 = ct * 128;
    const int b    = ct >> 9;
    const int barid = 3 + half;

    uint32_t* smu = (uint32_t*)smem;
    float*    smf = (float*)smem;
    const int A0 = OFF_A / 4, W0 = OFF_W / 4, F0 = OFF_F / 4;
    const uint32_t buf_b[2] = { smb + (half ? OFF_H0 : OFF_L0),
                                smb + (half ? OFF_H1 : OFF_L1) };
    const int bufw[2] = { (half ? OFF_H0 : OFF_L0) / 4,
                          (half ? OFF_H1 : OFF_L1) / 4 };

    // ---- stage A once (tf32-rounded, k-permuted within 8) ----
    for (int it = 0; it < 32; it++) {
        int idx = it * 256 + t;              // 128 rows x 64 float4
        int row = idx >> 6, c4 = idx & 63;
        float4 v = *(const float4*)&x[((size_t)(tok0 + row)) * CC + c4 * 4];
        uint32_t* d = &smu[A0 + row * AST + (c4 >> 1) * 8 + (c4 & 1)];
        d[0] = cvt_tf32(v.x); d[2] = cvt_tf32(v.y);
        d[4] = cvt_tf32(v.z); d[6] = cvt_tf32(v.w);
    }
    __syncthreads();

    for (int h = 0; h < HH; h++) {
        const float* img = g_Btf + (size_t)(h * 128 + half * 64) * 256;
        // prefetch slab 0
#pragma unroll
        for (int rr = 0; rr < 8; rr++) {
            int idx = rr * 128 + t128;
            int row = idx >> 4, c4 = idx & 15;
            CP_ASYNC16(buf_b[0] + (uint32_t)(row * 288 + c4 * 16),
                       img + (size_t)row * 256 + c4 * 4);
        }
        CP_COMMIT();

        // per-head scalars (overlap with prefetch)
        float tmp = temperature[h];
        tmp = fminf(fmaxf(tmp, 0.5f), 5.0f);
        const float invt = __fdividef(1.0f, tmp);
        float bias16[16];
#pragma unroll
        for (int nt = 0; nt < 8; nt++)
#pragma unroll
            for (int e = 0; e < 2; e++)
                bias16[nt * 2 + e] = half ? bfx[h * DD + nt * 8 + 2 * q + e]
                                          : g_beff[h][nt * 8 + 2 * q + e];

        float c[2][8][4];
#pragma unroll
        for (int i = 0; i < 2; i++)
#pragma unroll
            for (int j = 0; j < 8; j++)
#pragma unroll
                for (int e = 0; e < 4; e++) c[i][j][e] = 0.0f;

        // ============ GEMM1 over 4 K-slabs (64 each), double-buffered ============
#pragma unroll
        for (int sl = 0; sl < 4; sl++) {
            if (sl < 3) {
                const float* s2 = img + (sl + 1) * 64;
#pragma unroll
                for (int rr = 0; rr < 8; rr++) {
                    int idx = rr * 128 + t128;
                    int row = idx >> 4, c4 = idx & 15;
                    CP_ASYNC16(buf_b[(sl + 1) & 1] + (uint32_t)(row * 288 + c4 * 16),
                               s2 + (size_t)row * 256 + c4 * 4);
                }
                CP_COMMIT();
                CP_WAIT1();
            } else {
                CP_WAIT0();
            }
            HALF_BAR(barid);

            const int bw = bufw[sl & 1];
#pragma unroll
            for (int ks = 0; ks < 8; ks++) {
                const int kcol = sl * 64 + ks * 8 + 2 * q;
                uint32_t a[2][4];
#pragma unroll
                for (int mt = 0; mt < 2; mt++) {
                    const int r0 = wml * 32 + mt * 16 + g;
                    uint2 lo = *(const uint2*)&smu[A0 + r0 * AST + kcol];
                    uint2 hi = *(const uint2*)&smu[A0 + (r0 + 8) * AST + kcol];
                    a[mt][0] = lo.x; a[mt][1] = hi.x;
                    a[mt][2] = lo.y; a[mt][3] = hi.y;
                }
#pragma unroll
                for (int nt = 0; nt < 8; nt++) {
                    uint2 bb = *(const uint2*)&smu[bw + (nt * 8 + g) * 72 + ks * 8 + 2 * q];
                    mma_tf32(c[0][nt], a[0], bb.x, bb.y);
                    mma_tf32(c[1][nt], a[1], bb.x, bb.y);
                }
            }
            HALF_BAR(barid);   // buffer reads done -> next prefetch may overwrite
        }

        // ============ softmax (low half -> w) / bias+store (high half -> f) ============
        float nacc[16];
#pragma unroll
        for (int i = 0; i < 16; i++) nacc[i] = 0.0f;

        if (half == 0) {
#pragma unroll
            for (int mt = 0; mt < 2; mt++)
#pragma unroll
                for (int rr = 0; rr < 2; rr++) {
                    const int tok = wml * 32 + mt * 16 + g + 8 * rr;
                    const int pos = (tok & ~7) + ((g & 3) << 1) + (g >> 2);
                    float pv[16];
                    float mx = -1e30f;
#pragma unroll
                    for (int nt = 0; nt < 8; nt++)
#pragma unroll
                        for (int e = 0; e < 2; e++) {
                            float p = (c[mt][nt][rr * 2 + e] + bias16[nt * 2 + e]) * invt;
                            pv[nt * 2 + e] = p;
                            mx = fmaxf(mx, p);
                        }
                    mx = fmaxf(mx, __shfl_xor_sync(0xffffffffu, mx, 1));
                    mx = fmaxf(mx, __shfl_xor_sync(0xffffffffu, mx, 2));
                    float sv = 0.0f;
#pragma unroll
                    for (int j = 0; j < 16; j++) { pv[j] = __expf(pv[j] - mx); sv += pv[j]; }
                    sv += __shfl_xor_sync(0xffffffffu, sv, 1);
                    sv += __shfl_xor_sync(0xffffffffu, sv, 2);
                    const float r = __fdividef(1.0f, sv);
#pragma unroll
                    for (int nt = 0; nt < 8; nt++)
#pragma unroll
                        for (int e = 0; e < 2; e++) {
                            float wv = pv[nt * 2 + e] * r;
                            nacc[nt * 2 + e] += wv;
                            smu[W0 + (nt * 8 + 2 * q + e) * 136 + pos] = cvt_tf32(wv);
                        }
                }
        } else {
#pragma unroll
            for (int mt = 0; mt < 2; mt++)
#pragma unroll
                for (int rr = 0; rr < 2; rr++) {
                    const int tok = wml * 32 + mt * 16 + g + 8 * rr;
                    const int pos = (tok & ~7) + ((g & 3) << 1) + (g >> 2);
#pragma unroll
                    for (int nt = 0; nt < 8; nt++)
#pragma unroll
                        for (int e = 0; e < 2; e++) {
                            float fv = c[mt][nt][rr * 2 + e] + bias16[nt * 2 + e];
                            smu[F0 + (nt * 8 + 2 * q + e) * 136 + pos] = cvt_tf32(fv);
                        }
                }
        }
        __syncthreads();

        // ============ rank update: acc[64 s][64 d] += w^T @ fx (K = 128 tok) ============
        {
            const int wm2 = wp & 3;
            const int wn2 = wp >> 2;
            float racc[4][4];
#pragma unroll
            for (int i = 0; i < 4; i++)
#pragma unroll
                for (int j = 0; j < 4; j++) racc[i][j] = 0.0f;

#pragma unroll 4
            for (int ks = 0; ks < 16; ks++) {
                const int kc = ks * 8 + 2 * q;
                uint32_t a[4];
                const int r0 = wm2 * 16 + g;
                uint2 lo = *(const uint2*)&smu[W0 + r0 * 136 + kc];
                uint2 hi = *(const uint2*)&smu[W0 + (r0 + 8) * 136 + kc];
                a[0] = lo.x; a[1] = hi.x; a[2] = lo.y; a[3] = hi.y;
#pragma unroll
                for (int nt = 0; nt < 4; nt++) {
                    uint2 bb = *(const uint2*)&smu[F0 + (wn2 * 32 + nt * 8 + g) * 136 + kc];
                    mma_tf32(racc[nt], a, bb.x, bb.y);
                }
            }

            const int abase = (b * HH + h) * SS;
#pragma unroll
            for (int nt = 0; nt < 4; nt++)
#pragma unroll
                for (int rr = 0; rr < 2; rr++)
#pragma unroll
                    for (int e = 0; e < 2; e++) {
                        int s = wm2 * 16 + g + 8 * rr;
                        int d = wn2 * 32 + nt * 8 + 2 * q + e;
                        atomicAdd(&g_acc[(abase + s) * DD + d], racc[nt][rr * 2 + e]);
                    }
        }

        // ---- norm reduce + atomics (low half only) ----
        if (half == 0) {
#pragma unroll
            for (int j = 0; j < 16; j++) {
                nacc[j] += __shfl_xor_sync(0xffffffffu, nacc[j], 4);
                nacc[j] += __shfl_xor_sync(0xffffffffu, nacc[j], 8);
                nacc[j] += __shfl_xor_sync(0xffffffffu, nacc[j], 16);
            }
            if (g == 0) {
                const int nb = (b * HH + h) * SS;
#pragma unroll
                for (int nt = 0; nt < 8; nt++)
#pragma unroll
                    for (int e = 0; e < 2; e++)
                        atomicAdd(&g_norm[nb + nt * 8 + 2 * q + e], nacc[nt * 2 + e]);
            }
        }
        __syncthreads();   // w/f protected until rank reads done; next head may restage
    }
}

// ------------------------------------------------------------ finalize
__global__ void finalize_kernel(float* __restrict__ out) {
    int i = blockIdx.x * blockDim.x + threadIdx.x;
    if (i < BB * HH * SS * DD)
        out[i] = g_acc[i] / (g_norm[i >> 6] + 0.01f);
}

// -------------------------------------------------------------- launch
extern "C" void kernel_launch(void* const* d_in, const int* in_sizes, int n_in,
                              void* d_out, int out_size) {
    const float* x           = (const float*)d_in[0];
    const float* Wx          = (const float*)d_in[1];
    const float* bx          = (const float*)d_in[2];
    const float* Wfx         = (const float*)d_in[3];
    const float* bfx         = (const float*)d_in[4];
    const float* Wslice      = (const float*)d_in[5];
    const float* bslice      = (const float*)d_in[6];
    const float* temperature = (const float*)d_in[7];
    float* out = (float*)d_out;

    cudaFuncSetAttribute(fused_main, cudaFuncAttributeMaxDynamicSharedMemorySize,
                         SMEM_TOTAL);

    zero_kernel<<<(BB * HH * SS * DD + 255) / 256, 256>>>();
    precompute_kernel<<<HH * CC + 1, 64>>>(Wx, bx, Wslice, bslice);
    build_bt<<<HH, 256>>>(Wfx);
    fused_main<<<NCTA, 256, SMEM_TOTAL>>>(x, bfx, temperature);
    finalize_kernel<<<(BB * HH * SS * DD + 255) / 256, 256>>>(out);
}